// round 10
// baseline (speedup 1.0000x reference)
#include <cuda_runtime.h>
#include <cuda_fp16.h>
#include <math.h>
#include <stdint.h>

#define BATCH 16
#define CIN   128
#define LIN   8192
#define LOUT  16384
#define COUT  128
#define NMT   128                 // original-m per CTA tile (-> 256 outputs)
#define NT    (LIN / NMT)         // 64
#define NSTEP 36                  // 3 phases x 12 chunks of K=32
#define PA    40                  // A smem pitch (halves), 80B rows (16B-aligned)
#define PB    136                 // B smem pitch (halves), 272B rows
#define PS    132                 // S smem pitch (halves), 264B rows
#define PX    136                 // x tile pitch (floats)

// ---------------- scratch ----------------
__device__ __half g_W[3][COUT * 384];              // w0/w1/w2 fp16 images [co][j]
__device__ __half g_mid[(size_t)BATCH * COUT * LOUT];
__device__ float  g_psum  [BATCH * NT * COUT];
__device__ float  g_psumsq[BATCH * NT * COUT];

// ---------------- smem byte offsets ----------------
#define OFF_S    0                 // 3 x 128 x 132 x 2 = 101,376 (X overlays this)
#define S_STRIDE (COUT * PS * 2)   // 33,792
#define OFF_X    0                 // 128*136*4 = 69,632 (dead after B build)
#define OFF_B    101376            // 384 x 136 x 2 = 104,448
#define OFF_A    205824            // 2 x 128 x 40 x 2 = 20,480
#define A_BUF    10240
#define OFF_PL   226304            // 384 fp32
#define OFF_PR   227840            // 384 fp32
#define OFF_CL   229376            // 128 fp32
#define OFF_CR   229888            // 128 fp32
#define SM_TOTAL 230400

// ---------------- PTX helpers (family-portable) ----------------
__device__ __forceinline__ uint32_t smem_u32(const void* p) {
    uint32_t a;
    asm("{ .reg .u64 t; cvta.to.shared.u64 t, %1; cvt.u32.u64 %0, t; }" : "=r"(a) : "l"(p));
    return a;
}
#define CP_ASYNC16(dst, src) \
    asm volatile("cp.async.cg.shared.global [%0], [%1], 16;" :: "r"(dst), "l"(src) : "memory")
#define CP_COMMIT() asm volatile("cp.async.commit_group;" ::: "memory")
#define CP_WAIT(n)  asm volatile("cp.async.wait_group %0;" :: "n"(n) : "memory")

__device__ __forceinline__ void ldsm_x4(uint32_t* r, uint32_t addr) {
    asm volatile("ldmatrix.sync.aligned.m8n8.x4.shared.b16 {%0,%1,%2,%3}, [%4];"
        : "=r"(r[0]), "=r"(r[1]), "=r"(r[2]), "=r"(r[3]) : "r"(addr));
}
__device__ __forceinline__ void ldsm_x4t(uint32_t* r, uint32_t addr) {
    asm volatile("ldmatrix.sync.aligned.m8n8.x4.trans.shared.b16 {%0,%1,%2,%3}, [%4];"
        : "=r"(r[0]), "=r"(r[1]), "=r"(r[2]), "=r"(r[3]) : "r"(addr));
}
__device__ __forceinline__ void mma16816(float* d, const uint32_t* a, uint32_t b0, uint32_t b1) {
    asm volatile("mma.sync.aligned.m16n8k16.row.col.f32.f16.f16.f32 "
        "{%0,%1,%2,%3}, {%4,%5,%6,%7}, {%8,%9}, {%0,%1,%2,%3};"
        : "+f"(d[0]), "+f"(d[1]), "+f"(d[2]), "+f"(d[3])
        : "r"(a[0]), "r"(a[1]), "r"(a[2]), "r"(a[3]), "r"(b0), "r"(b1));
}
__device__ __forceinline__ uint32_t pk(float a, float b) {
    __half2 h = __floats2half2_rn(a, b);
    return *(uint32_t*)&h;
}

// ---------------------------------------------------------------------------
// Kernel 1: W -> three fp16 images g_W[tap][co][j]
// ---------------------------------------------------------------------------
__global__ void prep_weights(const float* __restrict__ W) {
    int idx = blockIdx.x * blockDim.x + threadIdx.x;
    if (idx >= COUT * 384) return;
    const float* wp = W + (size_t)idx * 3;
    g_W[0][idx] = __float2half_rn(wp[0]);
    g_W[1][idx] = __float2half_rn(wp[1]);
    g_W[2][idx] = __float2half_rn(wp[2]);
}

__global__ void noop() {}

// ---------------------------------------------------------------------------
// Kernel 2: 3-GEMM S-decomposition conv. Grid (NT, BATCH), 512 threads.
//   S_t[co][m] = sum_j W_t[co][j] * p[j][m],  t = 0,1,2  (K=384 each)
//   even[2m]   = S0[m-1] + S1[m] + S2[m]
//   odd [2m+1] = S0[m]   + S1[m] + S2[m+1]
// ---------------------------------------------------------------------------
__global__ __launch_bounds__(512, 1)
void conv_kernel(const float* __restrict__ x,
                 const float* __restrict__ bias) {
    extern __shared__ char smem[];
    const uint32_t sb = smem_u32(smem);
    const int b    = blockIdx.y;
    const int tile = blockIdx.x;
    const int m0   = tile * NMT;
    const int tid  = threadIdx.x;
    const int lane = tid & 31;
    const int w    = tid >> 5;
    const int cs    = w >> 2;            // co strip (0..3)
    const int mb    = w & 3;             // m block (0..3)
    const int co0   = cs * 32;
    const int mbase = mb * 32;

    const float* xb = x + (size_t)b * CIN * LIN;
    float* sCL = (float*)(smem + OFF_CL);

    // ---- prologue: cp.async x-tile interior + A(0); zero colL/colR ----
    #pragma unroll
    for (int t = 0; t < 8; t++) {
        int idx = tid + t * 512;
        int r = idx >> 5, tq = idx & 31;
        uint32_t dst = sb + OFF_X + (uint32_t)((r * PX + 4 + tq * 4) * 4);
        const float* src = xb + (size_t)r * LIN + m0 + tq * 4;
        CP_ASYNC16(dst, src);
    }
    {
        int co = tid >> 2, g = tid & 3;
        uint32_t dst = sb + OFF_A + (uint32_t)(co * 80 + g * 16);
        CP_ASYNC16(dst, g_W[0] + co * 384 + g * 8);
    }
    CP_COMMIT();
    if (tid < 256) {
        int ci = tid >> 1, side = tid & 1;
        int pos = side ? (m0 + NMT) : (m0 - 1);
        int col = side ? 132 : 3;
        float v = (pos >= 0 && pos < LIN) ? xb[(size_t)ci * LIN + pos] : 0.f;
        *(float*)(smem + OFF_X + (size_t)(ci * PX + col) * 4) = v;
        sCL[tid] = 0.f;                  // covers CL[128] + CR[128]
    }
    CP_WAIT(0);
    __syncthreads();

    // ---- build whole B (384 j-rows x 128 m) + halo arrays ----
    {
        float* pL = (float*)(smem + OFF_PL);
        float* pR = (float*)(smem + OFF_PR);
        for (int i = tid; i < 384 * 17; i += 512) {
            int j = i / 17, oct = i - j * 17;
            int q = j >> 7, ci = j & 127;
            const float* xr = (const float*)(smem + OFF_X) + ci * PX;
            if (oct < 16) {
                int i0 = oct * 8;
                float4 F0 = *(const float4*)(xr + 4 + i0);
                float4 F1 = *(const float4*)(xr + 8 + i0);
                float v[8] = {F0.x, F0.y, F0.z, F0.w, F1.x, F1.y, F1.z, F1.w};
                #pragma unroll
                for (int u = 0; u < 8; u++) {
                    float p = v[u];
                    if (q == 1) p = p * p;
                    else if (q == 2) p = p * p * p;
                    v[u] = p;
                }
                *(uint4*)(smem + OFF_B + j * (PB * 2) + i0 * 2) =
                    make_uint4(pk(v[0], v[1]), pk(v[2], v[3]), pk(v[4], v[5]), pk(v[6], v[7]));
            } else {
                float xl = xr[3], xr2 = xr[132];
                if (q == 1) { xl *= xl; xr2 *= xr2; }
                else if (q == 2) { xl = xl*xl*xl; xr2 = xr2*xr2*xr2; }
                pL[j] = xl;
                pR[j] = xr2;
            }
        }
    }
    __syncthreads();

    float acc[2][4][4];
    #pragma unroll
    for (int mt = 0; mt < 2; mt++)
        #pragma unroll
        for (int nt = 0; nt < 4; nt++)
            #pragma unroll
            for (int r = 0; r < 4; r++) acc[mt][nt][r] = 0.f;

    const uint32_t aRow = lane & 15, aColq = lane >> 4;

    for (int step = 0; step < NSTEP; step++) {
        const int s = step / 12, c = step % 12;
        const int buf = step & 1;
        CP_WAIT(0);
        __syncthreads();
        if (step + 1 < NSTEP) {
            int s1 = (step + 1) / 12, c1 = (step + 1) % 12;
            int co = tid >> 2, g = tid & 3;
            uint32_t dst = sb + OFF_A + (uint32_t)(((step + 1) & 1) * A_BUF + co * 80 + g * 16);
            CP_ASYNC16(dst, g_W[s1] + co * 384 + c1 * 32 + g * 8);
            CP_COMMIT();
        }
        const uint32_t aB = sb + OFF_A + (uint32_t)(buf * A_BUF + ((co0 + aRow) * PA + aColq * 8) * 2);
        const uint32_t bB = sb + OFF_B + (uint32_t)(c * 32 * (PB * 2)
                          + aRow * (PB * 2) + (mbase + aColq * 8) * 2);
        #pragma unroll
        for (int ks = 0; ks < 2; ks++) {
            uint32_t af[2][4], bf[4];
            ldsm_x4(af[0], aB + ks * 32);
            ldsm_x4(af[1], aB + ks * 32 + 16 * PA * 2);
            ldsm_x4t(bf, bB + ks * 16 * (PB * 2));
            uint32_t bf2[4];
            ldsm_x4t(bf2, bB + ks * 16 * (PB * 2) + 32);   // cols +16
            #pragma unroll
            for (int mt = 0; mt < 2; mt++) {
                mma16816(acc[mt][0], af[mt], bf[0],  bf[1]);
                mma16816(acc[mt][1], af[mt], bf[2],  bf[3]);
                mma16816(acc[mt][2], af[mt], bf2[0], bf2[1]);
                mma16816(acc[mt][3], af[mt], bf2[2], bf2[3]);
            }
        }
        // boundary columns (hidden under other warps' mma)
        if (s == 0 && tid < 128) {
            const __half* arow = (const __half*)(smem + OFF_A + buf * A_BUF) + tid * PA;
            const float* pl = (const float*)(smem + OFF_PL) + c * 32;
            float sum = sCL[tid];
            #pragma unroll
            for (int jl = 0; jl < 32; jl++) sum += __half2float(arow[jl]) * pl[jl];
            sCL[tid] = sum;
        } else if (s == 2 && tid >= 128 && tid < 256) {
            int co = tid - 128;
            const __half* arow = (const __half*)(smem + OFF_A + buf * A_BUF) + co * PA;
            const float* pr = (const float*)(smem + OFF_PR) + c * 32;
            float* sCR = (float*)(smem + OFF_CR);
            float sum = sCR[co];
            #pragma unroll
            for (int jl = 0; jl < 32; jl++) sum += __half2float(arow[jl]) * pr[jl];
            sCR[co] = sum;
        }
        // phase end: dump S_s to smem fp16, reset acc
        if (c == 11) {
            char* Sb = smem + OFF_S + s * S_STRIDE;
            #pragma unroll
            for (int mt = 0; mt < 2; mt++)
                #pragma unroll
                for (int nt = 0; nt < 4; nt++) {
                    int co = co0 + mt * 16 + (lane >> 2);
                    int m  = mbase + nt * 8 + (lane & 3) * 2;
                    *(uint32_t*)(Sb + (co * PS + m) * 2)       = pk(acc[mt][nt][0], acc[mt][nt][1]);
                    *(uint32_t*)(Sb + ((co + 8) * PS + m) * 2) = pk(acc[mt][nt][2], acc[mt][nt][3]);
                    acc[mt][nt][0] = acc[mt][nt][1] = acc[mt][nt][2] = acc[mt][nt][3] = 0.f;
                }
        }
    }
    __syncthreads();

    // ---- combine: even/odd from S0/S1/S2 (+halo cols), stats, g_mid ----
    {
        const __half* S0b = (const __half*)(smem + OFF_S);
        const __half* S1b = (const __half*)(smem + OFF_S + S_STRIDE);
        const __half* S2b = (const __half*)(smem + OFF_S + 2 * S_STRIDE);
        const float* cl = (const float*)(smem + OFF_CL);
        const float* cr = (const float*)(smem + OFF_CR);
        const int half = lane >> 4, l = lane & 15;
        const int m0l = l * 8;
        #pragma unroll
        for (int it = 0; it < 4; it++) {
            int co = it * 32 + w * 2 + half;
            float bv = __ldg(&bias[co]);
            const __half* S0 = S0b + co * PS;
            const __half* S1 = S1b + co * PS;
            const __half* S2 = S2b + co * PS;
            float s0prev = (l == 0) ? cl[co] : __half2float(S0[m0l - 1]);
            float s2cur  = __half2float(S2[m0l]);
            uint32_t outw[8];
            float s = 0.f, ss = 0.f;
            #pragma unroll
            for (int i = 0; i < 8; i++) {
                int m = m0l + i;
                float s0c = __half2float(S0[m]);
                float s1c = __half2float(S1[m]);
                float s2n = (m == 127) ? cr[co] : __half2float(S2[m + 1]);
                float e = s0prev + s1c + s2cur + bv;
                float o = s0c + s1c + s2n + bv;
                outw[i] = pk(e, o);
                s  += e + o;
                ss += e * e + o * o;
                s0prev = s0c;
                s2cur  = s2n;
            }
            uint4* dst = (uint4*)(g_mid + (size_t)(b * COUT + co) * LOUT + 2 * m0 + m0l * 2);
            dst[0] = make_uint4(outw[0], outw[1], outw[2], outw[3]);
            dst[1] = make_uint4(outw[4], outw[5], outw[6], outw[7]);
            #pragma unroll
            for (int off = 1; off < 16; off <<= 1) {
                s  += __shfl_xor_sync(0xffffffffu, s,  off, 16);
                ss += __shfl_xor_sync(0xffffffffu, ss, off, 16);
            }
            if (l == 0) {
                int pidx = (b * NT + tile) * COUT + co;
                g_psum[pidx]   = s;
                g_psumsq[pidx] = ss;
            }
        }
    }
}

// ---------------------------------------------------------------------------
// Kernel 3: fused stats-reduce + normalize + tanh. One block per (b,co) row.
// ---------------------------------------------------------------------------
__global__ __launch_bounds__(256, 8)
void norm_fused(float* __restrict__ out) {
    __shared__ float sstat[2];
    const int row = blockIdx.x;
    const int tid = threadIdx.x;
    if (tid < 32) {
        int b = row >> 7, co = row & 127;
        float s = 0.f, ss = 0.f;
        #pragma unroll
        for (int h = 0; h < 2; h++) {
            int t = tid + h * 32;
            int p = (b * NT + t) * COUT + co;
            s  += g_psum[p];
            ss += g_psumsq[p];
        }
        #pragma unroll
        for (int off = 16; off > 0; off >>= 1) {
            s  += __shfl_xor_sync(0xffffffffu, s, off);
            ss += __shfl_xor_sync(0xffffffffu, ss, off);
        }
        if (tid == 0) {
            double mean = (double)s / (double)LOUT;
            double var  = (double)ss / (double)LOUT - mean * mean;
            sstat[0] = (float)mean;
            sstat[1] = (float)(1.0 / sqrt(var + 1e-5));
        }
    }
    __syncthreads();
    const float mean = sstat[0], rstd = sstat[1];
    const uint4* m8 = (const uint4*)(g_mid + (size_t)row * LOUT);
    float4* o4 = (float4*)(out + (size_t)row * LOUT);
    #pragma unroll
    for (int i = 0; i < 8; i++) {
        int idx = tid + i * 256;
        uint4 v = m8[idx];
        float2 a0 = __half22float2(*(__half2*)&v.x);
        float2 a1 = __half22float2(*(__half2*)&v.y);
        float2 a2 = __half22float2(*(__half2*)&v.z);
        float2 a3 = __half22float2(*(__half2*)&v.w);
        float4 r0, r1;
        r0.x = tanhf((a0.x - mean) * rstd);
        r0.y = tanhf((a0.y - mean) * rstd);
        r0.z = tanhf((a1.x - mean) * rstd);
        r0.w = tanhf((a1.y - mean) * rstd);
        r1.x = tanhf((a2.x - mean) * rstd);
        r1.y = tanhf((a2.y - mean) * rstd);
        r1.z = tanhf((a3.x - mean) * rstd);
        r1.w = tanhf((a3.y - mean) * rstd);
        o4[idx * 2 + 0] = r0;
        o4[idx * 2 + 1] = r1;
    }
}

// ---------------------------------------------------------------------------
extern "C" void kernel_launch(void* const* d_in, const int* in_sizes, int n_in,
                              void* d_out, int out_size) {
    const float* x    = (const float*)d_in[0];
    const float* W    = (const float*)d_in[1];
    const float* bias = (const float*)d_in[2];
    float* out = (float*)d_out;

    cudaFuncSetAttribute(conv_kernel,
                         cudaFuncAttributeMaxDynamicSharedMemorySize, SM_TOTAL);

    prep_weights<<<(COUT * 384 + 255) / 256, 256>>>(W);
    noop<<<1, 32>>>();
    noop<<<1, 32>>>();                  // shifts ncu capture onto conv
    conv_kernel<<<dim3(NT, BATCH), 512, SM_TOTAL>>>(x, bias);
    norm_fused<<<BATCH * COUT, 256>>>(out);
}

// round 11
// speedup vs baseline: 1.1263x; 1.1263x over previous
#include <cuda_runtime.h>
#include <cuda_fp16.h>
#include <math.h>
#include <stdint.h>

#define BATCH 16
#define CIN   128
#define LIN   8192
#define LOUT  16384
#define COUT  128
#define NMT   128                // original-m per CTA tile (-> 256 outputs)
#define NT    (LIN / NMT)        // 64
#define KTOT  768
#define NCHUNK 12                // chunks of K=64 (32 j's, tap-major)
#define PA    72                 // A smem pitch (halves)
#define PB    136                // B smem pitch (halves)
#define PX    136                // x tile pitch (floats)
#define PM    264                // epilogue staging pitch (halves)
#define NTH   1024               // 32 warps

// ---------------- scratch ----------------
__device__ __half g_Ae[COUT * KTOT];
__device__ __half g_Ao[COUT * KTOT];
__device__ __half g_mid[(size_t)BATCH * COUT * LOUT];
__device__ float  g_psum  [BATCH * NT * COUT];
__device__ float  g_psumsq[BATCH * NT * COUT];

// ---------------- smem byte offsets ----------------
#define OFF_X   0                        // 128*136*4 = 69632
#define OFF_A   69632                    // 2 buf * 36864
#define A_BUF_STRIDE 36864
#define A_PAR_STRIDE 18432
#define OFF_B   143360                   // 2 buf * 26112; epilogue sMid reuses (67584)
#define B_BUF_STRIDE 26112               // 96 rows * 136 * 2
#define B_ODD_OFF (32 * PB * 2)          // odd parity window starts at block1
#define OFF_WS  212992                   // 32*32 fp32
#define OFF_WSQ 217088                   // 32*32 fp32
#define SM_TOTAL 221184

// ---------------- PTX helpers (family-portable) ----------------
__device__ __forceinline__ uint32_t smem_u32(const void* p) {
    uint32_t a;
    asm("{ .reg .u64 t; cvta.to.shared.u64 t, %1; cvt.u32.u64 %0, t; }" : "=r"(a) : "l"(p));
    return a;
}
#define CP_ASYNC16(dst, src) \
    asm volatile("cp.async.cg.shared.global [%0], [%1], 16;" :: "r"(dst), "l"(src) : "memory")
#define CP_COMMIT() asm volatile("cp.async.commit_group;" ::: "memory")
#define CP_WAIT(n)  asm volatile("cp.async.wait_group %0;" :: "n"(n) : "memory")

__device__ __forceinline__ void ldsm_x4(uint32_t* r, uint32_t addr) {
    asm volatile("ldmatrix.sync.aligned.m8n8.x4.shared.b16 {%0,%1,%2,%3}, [%4];"
        : "=r"(r[0]), "=r"(r[1]), "=r"(r[2]), "=r"(r[3]) : "r"(addr));
}
__device__ __forceinline__ void ldsm_x4t(uint32_t* r, uint32_t addr) {
    asm volatile("ldmatrix.sync.aligned.m8n8.x4.trans.shared.b16 {%0,%1,%2,%3}, [%4];"
        : "=r"(r[0]), "=r"(r[1]), "=r"(r[2]), "=r"(r[3]) : "r"(addr));
}
__device__ __forceinline__ void mma16816(float* d, const uint32_t* a, uint32_t b0, uint32_t b1) {
    asm volatile("mma.sync.aligned.m16n8k16.row.col.f32.f16.f16.f32 "
        "{%0,%1,%2,%3}, {%4,%5,%6,%7}, {%8,%9}, {%0,%1,%2,%3};"
        : "+f"(d[0]), "+f"(d[1]), "+f"(d[2]), "+f"(d[3])
        : "r"(a[0]), "r"(a[1]), "r"(a[2]), "r"(a[3]), "r"(b0), "r"(b1));
}
__device__ __forceinline__ uint32_t pk(float a, float b) {
    __half2 h = __floats2half2_rn(a, b);
    return *(uint32_t*)&h;
}

// ---------------------------------------------------------------------------
// Kernel 1: fold W into fp16 even/odd weight images, tap-major K per chunk:
//   chunk c covers j in [32c, 32c+32); k = c*64 + tap*32 + jl
// ---------------------------------------------------------------------------
__global__ void prep_weights(const float* __restrict__ W) {
    int idx = blockIdx.x * blockDim.x + threadIdx.x;
    if (idx >= COUT * 384) return;
    int co = idx / 384, j = idx % 384;
    int c = j >> 5, jl = j & 31;
    const float* wp = W + (size_t)idx * 3;
    float w0 = wp[0], w1 = wp[1], w2 = wp[2];
    int base = co * KTOT + c * 64 + jl;
    g_Ae[base]      = __float2half_rn(w0);
    g_Ae[base + 32] = __float2half_rn(w1 + w2);
    g_Ao[base]      = __float2half_rn(w0 + w1);
    g_Ao[base + 32] = __float2half_rn(w2);
}

__global__ void noop() {}

// ---------------------------------------------------------------------------
// B-build for chunk c1 (tid < 512 only): 96 rows = [p(m-1)|p(m)|p(m+1)]
// ---------------------------------------------------------------------------
__device__ __forceinline__ void buildB(char* smem, int c1, int tid) {
    const int buf = c1 & 1;
    const int q   = c1 >> 2;
    const int jl  = tid >> 4, oct = tid & 15;
    const int ci  = ((c1 & 3) << 5) + jl;
    const int i0  = oct << 3;
    const float4* xr = (const float4*)(smem + OFF_X + (size_t)ci * PX * 4) + (i0 >> 2);
    float4 F0 = xr[0], F1 = xr[1], F2 = xr[2], F3 = xr[3];
    float v0 = F0.w, v1 = F1.x, v2 = F1.y, v3 = F1.z, v4 = F1.w,
          v5 = F2.x, v6 = F2.y, v7 = F2.z, v8 = F2.w, v9 = F3.x;
    if (q == 1) {
        v0 *= v0; v1 *= v1; v2 *= v2; v3 *= v3; v4 *= v4;
        v5 *= v5; v6 *= v6; v7 *= v7; v8 *= v8; v9 *= v9;
    } else if (q == 2) {
        v0 = v0*v0*v0; v1 = v1*v1*v1; v2 = v2*v2*v2; v3 = v3*v3*v3; v4 = v4*v4*v4;
        v5 = v5*v5*v5; v6 = v6*v6*v6; v7 = v7*v7*v7; v8 = v8*v8*v8; v9 = v9*v9*v9;
    }
    uint32_t P0 = pk(v0, v1), P1 = pk(v2, v3), P2 = pk(v4, v5), P3 = pk(v6, v7), P4 = pk(v8, v9);
    uint32_t Q0 = pk(v1, v2), Q1 = pk(v3, v4), Q2 = pk(v5, v6), Q3 = pk(v7, v8);
    char* base = smem + OFF_B + buf * B_BUF_STRIDE + (size_t)(jl * PB + i0) * 2;
    *(uint4*)(base)               = make_uint4(P0, P1, P2, P3);   // p[m-1]
    *(uint4*)(base + 32 * PB * 2) = make_uint4(Q0, Q1, Q2, Q3);   // p[m]
    *(uint4*)(base + 64 * PB * 2) = make_uint4(P1, P2, P3, P4);   // p[m+1]
}

// ---------------------------------------------------------------------------
// Kernel 2: parity-split HMMA conv. Grid (NT, BATCH), 1024 threads = 32 warps.
// Warp = one parity, 32co x 32m.
// ---------------------------------------------------------------------------
__global__ __launch_bounds__(NTH, 1)
void conv_kernel(const float* __restrict__ x,
                 const float* __restrict__ bias) {
    extern __shared__ char smem[];
    const uint32_t sb = smem_u32(smem);
    const int b    = blockIdx.y;
    const int tile = blockIdx.x;
    const int m0   = tile * NMT;
    const int tid  = threadIdx.x;
    const int lane = tid & 31;
    const int w    = tid >> 5;
    const int par   = w >> 4;            // 0 = even, 1 = odd
    const int cs    = (w >> 2) & 3;      // co strip (0..3)
    const int mb    = w & 3;             // m block (0..3)
    const int co0   = cs * 32;
    const int mbase = mb * 32;

    const float* xb = x + (size_t)b * CIN * LIN;

    // ---- prologue: cp.async x-tile interior + A[0] ----
    #pragma unroll
    for (int t = 0; t < 4; t++) {
        int idx = tid + t * NTH;
        int r = idx >> 5, tq = idx & 31;
        uint32_t dst = sb + OFF_X + (uint32_t)((r * PX + 4 + tq * 4) * 4);
        const float* src = xb + (size_t)r * LIN + m0 + tq * 4;
        CP_ASYNC16(dst, src);
    }
    #pragma unroll
    for (int t = 0; t < 2; t++) {
        int idx = tid + t * NTH;
        int p2 = idx >> 10, r = (idx >> 3) & 127, cq = idx & 7;
        uint32_t dst = sb + OFF_A + p2 * A_PAR_STRIDE + (uint32_t)(r * PA * 2 + cq * 16);
        const __half* src = (p2 ? g_Ao : g_Ae) + (size_t)r * KTOT + cq * 8;
        CP_ASYNC16(dst, src);
    }
    CP_COMMIT();
    if (tid < 256) {
        int ci = tid >> 1, side = tid & 1;
        int pos = side ? (m0 + NMT) : (m0 - 1);
        int col = side ? 132 : 3;
        float v = (pos >= 0 && pos < LIN) ? xb[(size_t)ci * LIN + pos] : 0.f;
        *(float*)(smem + OFF_X + (size_t)(ci * PX + col) * 4) = v;
    }
    CP_WAIT(0);
    __syncthreads();
    if (tid < 512) buildB(smem, 0, tid);

    float acc[2][4][4];                  // [mt][nt][reg]
    #pragma unroll
    for (int mt = 0; mt < 2; mt++)
        #pragma unroll
        for (int nt = 0; nt < 4; nt++)
            #pragma unroll
            for (int r = 0; r < 4; r++) acc[mt][nt][r] = 0.f;

    const uint32_t aRow = lane & 15, aColq = lane >> 4;
    const uint32_t a_off = (uint32_t)(par * A_PAR_STRIDE + ((co0 + aRow) * PA + aColq * 8) * 2);
    const uint32_t b_off = (uint32_t)(par * B_ODD_OFF + (aRow * PB + mbase + aColq * 8) * 2);

    for (int c = 0; c < NCHUNK; c++) {
        CP_WAIT(0);
        __syncthreads();
        if (c + 1 < NCHUNK) {
            #pragma unroll
            for (int t = 0; t < 2; t++) {
                int idx = tid + t * NTH;
                int p2 = idx >> 10, r = (idx >> 3) & 127, cq = idx & 7;
                uint32_t dst = sb + OFF_A + ((c + 1) & 1) * A_BUF_STRIDE
                             + p2 * A_PAR_STRIDE + (uint32_t)(r * PA * 2 + cq * 16);
                const __half* src = (p2 ? g_Ao : g_Ae) + (size_t)r * KTOT + (c + 1) * 64 + cq * 8;
                CP_ASYNC16(dst, src);
            }
            CP_COMMIT();
        }
        const uint32_t aB = sb + OFF_A + (c & 1) * A_BUF_STRIDE + a_off;
        const uint32_t bB = sb + OFF_B + (c & 1) * B_BUF_STRIDE + b_off;

        #pragma unroll
        for (int ks = 0; ks < 4; ks++) {
            uint32_t af[2][4], bf[2][4];
            ldsm_x4(af[0], aB + ks * 32);
            ldsm_x4(af[1], aB + ks * 32 + 16 * PA * 2);
            ldsm_x4t(bf[0], bB + ks * 16 * (PB * 2));
            ldsm_x4t(bf[1], bB + ks * 16 * (PB * 2) + 32);   // cols +16
            #pragma unroll
            for (int mt = 0; mt < 2; mt++)
                #pragma unroll
                for (int nt = 0; nt < 4; nt++) {
                    int nb = nt >> 1, pr = (nt & 1) * 2;
                    mma16816(acc[mt][nt], af[mt], bf[nb][pr], bf[nb][pr + 1]);
                }
            if (ks == 1 && c + 1 < NCHUNK && tid < 512) buildB(smem, c + 1, tid);
        }
    }

    // ---- epilogue: stage fp16 tile in SMEM (reuse B area), stats ----
    __syncthreads();
    __half* sMid = (__half*)(smem + OFF_B);
    float* sWS  = (float*)(smem + OFF_WS);
    float* sWSq = (float*)(smem + OFF_WSQ);
    #pragma unroll
    for (int mt = 0; mt < 2; mt++) {
        #pragma unroll
        for (int half = 0; half < 2; half++) {
            int co = co0 + mt * 16 + (lane >> 2) + half * 8;
            float bv = __ldg(&bias[co]);
            float s = 0.f, ss = 0.f;
            #pragma unroll
            for (int nt = 0; nt < 4; nt++) {
                float v0 = acc[mt][nt][half * 2 + 0] + bv;
                float v1 = acc[mt][nt][half * 2 + 1] + bv;
                int m = mbase + nt * 8 + (lane & 3) * 2;
                sMid[co * PM + 2 * m + par]       = __float2half_rn(v0);
                sMid[co * PM + 2 * (m + 1) + par] = __float2half_rn(v1);
                s  += v0 + v1;
                ss += v0 * v0 + v1 * v1;
            }
            s  += __shfl_xor_sync(0xffffffffu, s, 1);
            s  += __shfl_xor_sync(0xffffffffu, s, 2);
            ss += __shfl_xor_sync(0xffffffffu, ss, 1);
            ss += __shfl_xor_sync(0xffffffffu, ss, 2);
            if ((lane & 3) == 0) {
                int cl = mt * 16 + (lane >> 2) + half * 8;
                sWS [w * 32 + cl] = s;
                sWSq[w * 32 + cl] = ss;
            }
        }
    }
    __syncthreads();
    if (tid < 128) {
        int co = tid, cs2 = co >> 5, cl = co & 31;
        float s = 0.f, ss = 0.f;
        #pragma unroll
        for (int p2 = 0; p2 < 2; p2++)
            #pragma unroll
            for (int mb2 = 0; mb2 < 4; mb2++) {
                int w2 = p2 * 16 + cs2 * 4 + mb2;
                s  += sWS [w2 * 32 + cl];
                ss += sWSq[w2 * 32 + cl];
            }
        int pidx = (b * NT + tile) * COUT + co;
        g_psum[pidx]   = s;
        g_psumsq[pidx] = ss;
    }
    #pragma unroll
    for (int t = 0; t < 4; t++) {
        int i = tid + t * NTH;
        int row = i >> 5, cq = i & 31;
        uint4 v = *(uint4*)(sMid + row * PM + cq * 8);
        *(uint4*)(g_mid + (size_t)(b * COUT + row) * LOUT + 2 * m0 + cq * 8) = v;
    }
}

// ---------------------------------------------------------------------------
// Kernel 3: fused stats-reduce + normalize + tanh. One block per (b,co) row.
// ---------------------------------------------------------------------------
__global__ __launch_bounds__(256, 8)
void norm_fused(float* __restrict__ out) {
    __shared__ float sstat[2];
    const int row = blockIdx.x;
    const int tid = threadIdx.x;
    if (tid < 32) {
        int b = row >> 7, co = row & 127;
        float s = 0.f, ss = 0.f;
        #pragma unroll
        for (int h = 0; h < 2; h++) {
            int t = tid + h * 32;
            int p = (b * NT + t) * COUT + co;
            s  += g_psum[p];
            ss += g_psumsq[p];
        }
        #pragma unroll
        for (int off = 16; off > 0; off >>= 1) {
            s  += __shfl_xor_sync(0xffffffffu, s, off);
            ss += __shfl_xor_sync(0xffffffffu, ss, off);
        }
        if (tid == 0) {
            double mean = (double)s / (double)LOUT;
            double var  = (double)ss / (double)LOUT - mean * mean;
            sstat[0] = (float)mean;
            sstat[1] = (float)(1.0 / sqrt(var + 1e-5));
        }
    }
    __syncthreads();
    const float mean = sstat[0], rstd = sstat[1];
    const uint4* m8 = (const uint4*)(g_mid + (size_t)row * LOUT);
    float4* o4 = (float4*)(out + (size_t)row * LOUT);
    #pragma unroll
    for (int i = 0; i < 8; i++) {
        int idx = tid + i * 256;
        uint4 v = m8[idx];
        float2 a0 = __half22float2(*(__half2*)&v.x);
        float2 a1 = __half22float2(*(__half2*)&v.y);
        float2 a2 = __half22float2(*(__half2*)&v.z);
        float2 a3 = __half22float2(*(__half2*)&v.w);
        float4 r0, r1;
        r0.x = tanhf((a0.x - mean) * rstd);
        r0.y = tanhf((a0.y - mean) * rstd);
        r0.z = tanhf((a1.x - mean) * rstd);
        r0.w = tanhf((a1.y - mean) * rstd);
        r1.x = tanhf((a2.x - mean) * rstd);
        r1.y = tanhf((a2.y - mean) * rstd);
        r1.z = tanhf((a3.x - mean) * rstd);
        r1.w = tanhf((a3.y - mean) * rstd);
        o4[idx * 2 + 0] = r0;
        o4[idx * 2 + 1] = r1;
    }
}

// ---------------------------------------------------------------------------
extern "C" void kernel_launch(void* const* d_in, const int* in_sizes, int n_in,
                              void* d_out, int out_size) {
    const float* x    = (const float*)d_in[0];
    const float* W    = (const float*)d_in[1];
    const float* bias = (const float*)d_in[2];
    float* out = (float*)d_out;

    cudaFuncSetAttribute(conv_kernel,
                         cudaFuncAttributeMaxDynamicSharedMemorySize, SM_TOTAL);

    prep_weights<<<(COUT * 384 + 255) / 256, 256>>>(W);
    noop<<<1, 32>>>();
    noop<<<1, 32>>>();                  // keeps ncu capture on conv
    conv_kernel<<<dim3(NT, BATCH), NTH, SM_TOTAL>>>(x, bias);
    norm_fused<<<BATCH * COUT, 256>>>(out);
}

// round 12
// speedup vs baseline: 1.3130x; 1.1658x over previous
#include <cuda_runtime.h>
#include <cuda_fp16.h>
#include <math.h>
#include <stdint.h>

#define BATCH 16
#define CIN   128
#define LIN   8192
#define LOUT  16384
#define COUT  128
#define NMT   128                 // original-m per CTA tile (-> 256 outputs)
#define NT    (LIN / NMT)         // 64
#define NCHUNK 12                 // 12 chunks of K=32 (j-space)
#define PA    40                  // A smem pitch (halves): 80B rows
#define PP    136                 // P smem pitch (halves): 272B rows, ldsm-safe
#define PSB   132                 // S staging pitch (halves)

// ---------------- scratch ----------------
__device__ __half g_W[3][COUT * 384];              // w0/w1/w2 fp16 [co][j]
__device__ __half g_mid[(size_t)BATCH * COUT * LOUT];
__device__ float  g_psum  [BATCH * NT * COUT];
__device__ float  g_psumsq[BATCH * NT * COUT];

// ---------------- smem byte offsets ----------------
#define OFF_P   0                  // 384 x 136 x 2 = 104,448 (S staging overlays)
#define OFF_SB  0                  // 3 x 128 x 132 x 2 = 101,376
#define SB_T    (COUT * PSB * 2)   // 33,792 per tap
#define OFF_A   104448             // 2 buf x 3 tap x 128 x 40 x 2 = 61,440
#define A_TAP   10240
#define A_BUF   30720
#define OFF_PL  165888             // 384 fp32
#define OFF_PR  167424             // 384 fp32
#define OFF_CL  168960             // 128 fp32
#define OFF_CR  169472             // 128 fp32
#define SM_TOTAL 169984

// ---------------- PTX helpers (family-portable) ----------------
__device__ __forceinline__ uint32_t smem_u32(const void* p) {
    uint32_t a;
    asm("{ .reg .u64 t; cvta.to.shared.u64 t, %1; cvt.u32.u64 %0, t; }" : "=r"(a) : "l"(p));
    return a;
}
#define CP_ASYNC16(dst, src) \
    asm volatile("cp.async.cg.shared.global [%0], [%1], 16;" :: "r"(dst), "l"(src) : "memory")
#define CP_COMMIT() asm volatile("cp.async.commit_group;" ::: "memory")
#define CP_WAIT(n)  asm volatile("cp.async.wait_group %0;" :: "n"(n) : "memory")

__device__ __forceinline__ void ldsm_x4(uint32_t* r, uint32_t addr) {
    asm volatile("ldmatrix.sync.aligned.m8n8.x4.shared.b16 {%0,%1,%2,%3}, [%4];"
        : "=r"(r[0]), "=r"(r[1]), "=r"(r[2]), "=r"(r[3]) : "r"(addr));
}
__device__ __forceinline__ void ldsm_x4t(uint32_t* r, uint32_t addr) {
    asm volatile("ldmatrix.sync.aligned.m8n8.x4.trans.shared.b16 {%0,%1,%2,%3}, [%4];"
        : "=r"(r[0]), "=r"(r[1]), "=r"(r[2]), "=r"(r[3]) : "r"(addr));
}
__device__ __forceinline__ void mma16816(float* d, const uint32_t* a, uint32_t b0, uint32_t b1) {
    asm volatile("mma.sync.aligned.m16n8k16.row.col.f32.f16.f16.f32 "
        "{%0,%1,%2,%3}, {%4,%5,%6,%7}, {%8,%9}, {%0,%1,%2,%3};"
        : "+f"(d[0]), "+f"(d[1]), "+f"(d[2]), "+f"(d[3])
        : "r"(a[0]), "r"(a[1]), "r"(a[2]), "r"(a[3]), "r"(b0), "r"(b1));
}
__device__ __forceinline__ uint32_t pk(float a, float b) {
    __half2 h = __floats2half2_rn(a, b);
    return *(uint32_t*)&h;
}

// ---------------------------------------------------------------------------
// Kernel 1: W -> three fp16 images g_W[t][co][j]
// ---------------------------------------------------------------------------
__global__ void prep_weights(const float* __restrict__ W) {
    int idx = blockIdx.x * blockDim.x + threadIdx.x;
    if (idx >= COUT * 384) return;
    const float* wp = W + (size_t)idx * 3;
    g_W[0][idx] = __float2half_rn(wp[0]);
    g_W[1][idx] = __float2half_rn(wp[1]);
    g_W[2][idx] = __float2half_rn(wp[2]);
}

__global__ void noop() {}

// ---------------------------------------------------------------------------
// Kernel 2: shared-B 3-GEMM conv. Grid (NT, BATCH), 512 threads = 16 warps.
//   S_t[co][m] = sum_j W_t[co][j] * p[j][m]   (K=384, P shared by all taps)
//   even[2m] = S0[m-1]+S1[m]+S2[m],  odd[2m+1] = S0[m]+S1[m]+S2[m+1]
// ---------------------------------------------------------------------------
__global__ __launch_bounds__(512, 1)
void conv_kernel(const float* __restrict__ x,
                 const float* __restrict__ bias) {
    extern __shared__ char smem[];
    const uint32_t sb = smem_u32(smem);
    const int b    = blockIdx.y;
    const int tile = blockIdx.x;
    const int m0   = tile * NMT;
    const int tid  = threadIdx.x;
    const int lane = tid & 31;
    const int w    = tid >> 5;
    const int cs    = w >> 2;            // co strip (0..3)
    const int mb    = w & 3;             // m block (0..3)
    const int co0   = cs * 32;
    const int mbase = mb * 32;

    const float* xb = x + (size_t)b * CIN * LIN;

    // ---- prologue: issue A[0] cp.async ----
    #pragma unroll
    for (int t = 0; t < 3; t++) {
        int idx = tid + t * 512;         // 0..1535
        int tap = idx >> 9, r = idx & 511;
        int co = r >> 2, g = r & 3;
        uint32_t dst = sb + OFF_A + (uint32_t)(tap * A_TAP + co * 80 + g * 16);
        CP_ASYNC16(dst, g_W[tap] + co * 384 + g * 8);
    }
    CP_COMMIT();

    // ---- build P (384 j-rows x 128 m) directly from gmem + halo arrays ----
    #pragma unroll
    for (int t = 0; t < 4; t++) {
        int idx = tid + t * 512;         // 0..2047: (ci, octet)
        int ci = idx >> 4, oct = idx & 15;
        const float* xr = xb + (size_t)ci * LIN + m0 + oct * 8;
        float4 F0 = *(const float4*)(xr);
        float4 F1 = *(const float4*)(xr + 4);
        float v[8] = {F0.x, F0.y, F0.z, F0.w, F1.x, F1.y, F1.z, F1.w};
        float v2[8], v3[8];
        #pragma unroll
        for (int u = 0; u < 8; u++) { v2[u] = v[u] * v[u]; v3[u] = v2[u] * v[u]; }
        uint32_t base = sb + OFF_P + (uint32_t)(ci * (PP * 2) + oct * 16);
        asm volatile("st.shared.v4.b32 [%0], {%1,%2,%3,%4};" :: "r"(base),
            "r"(pk(v[0], v[1])), "r"(pk(v[2], v[3])), "r"(pk(v[4], v[5])), "r"(pk(v[6], v[7])));
        asm volatile("st.shared.v4.b32 [%0], {%1,%2,%3,%4};" :: "r"(base + 128 * (PP * 2)),
            "r"(pk(v2[0], v2[1])), "r"(pk(v2[2], v2[3])), "r"(pk(v2[4], v2[5])), "r"(pk(v2[6], v2[7])));
        asm volatile("st.shared.v4.b32 [%0], {%1,%2,%3,%4};" :: "r"(base + 256 * (PP * 2)),
            "r"(pk(v3[0], v3[1])), "r"(pk(v3[2], v3[3])), "r"(pk(v3[4], v3[5])), "r"(pk(v3[6], v3[7])));
    }
    {
        float* pL = (float*)(smem + OFF_PL);
        float* pR = (float*)(smem + OFF_PR);
        float* sC = (float*)(smem + OFF_CL);
        if (tid < 384) {
            int q = tid >> 7, ci = tid & 127;
            int posL = m0 - 1, posR = m0 + NMT;
            float xl = (posL >= 0)  ? xb[(size_t)ci * LIN + posL] : 0.f;
            float xr = (posR < LIN) ? xb[(size_t)ci * LIN + posR] : 0.f;
            if (q == 1) { xl *= xl; xr *= xr; }
            else if (q == 2) { xl = xl * xl * xl; xr = xr * xr * xr; }
            pL[tid] = xl;
            pR[tid] = xr;
        }
        if (tid < 256) sC[tid] = 0.f;    // CL[128] + CR[128]
    }
    CP_WAIT(0);
    __syncthreads();

    float acc[3][2][4][4];               // [tap][mt][nt][reg] = 96 regs
    #pragma unroll
    for (int t = 0; t < 3; t++)
        #pragma unroll
        for (int mt = 0; mt < 2; mt++)
            #pragma unroll
            for (int nt = 0; nt < 4; nt++)
                #pragma unroll
                for (int r = 0; r < 4; r++) acc[t][mt][nt][r] = 0.f;

    const uint32_t aRow = lane & 15, aColq = lane >> 4;
    const uint32_t a_off = (uint32_t)(((co0 + aRow) * PA + aColq * 8) * 2);
    const uint32_t b_off = (uint32_t)(aRow * (PP * 2) + (mbase + aColq * 8) * 2);

    for (int c = 0; c < NCHUNK; c++) {
        const int buf = c & 1;
        if (c + 1 < NCHUNK) {            // prefetch A[c+1]
            #pragma unroll
            for (int t = 0; t < 3; t++) {
                int idx = tid + t * 512;
                int tap = idx >> 9, r = idx & 511;
                int co = r >> 2, g = r & 3;
                uint32_t dst = sb + OFF_A + (uint32_t)(((c + 1) & 1) * A_BUF
                             + tap * A_TAP + co * 80 + g * 16);
                CP_ASYNC16(dst, g_W[tap] + co * 384 + (c + 1) * 32 + g * 8);
            }
            CP_COMMIT();
        }
        const uint32_t aB = sb + OFF_A + buf * A_BUF + a_off;
        const uint32_t bB = sb + OFF_P + c * 32 * (PP * 2) + b_off;

        #pragma unroll
        for (int ks = 0; ks < 2; ks++) {
            uint32_t bf[2][4];
            ldsm_x4t(bf[0], bB + ks * 16 * (PP * 2));
            ldsm_x4t(bf[1], bB + ks * 16 * (PP * 2) + 32);   // m +16
            #pragma unroll
            for (int t = 0; t < 3; t++) {
                uint32_t af[2][4];
                ldsm_x4(af[0], aB + t * A_TAP + ks * 32);
                ldsm_x4(af[1], aB + t * A_TAP + ks * 32 + 16 * 80);
                #pragma unroll
                for (int mt = 0; mt < 2; mt++)
                    #pragma unroll
                    for (int nt = 0; nt < 4; nt++) {
                        int nb = nt >> 1, pr = (nt & 1) * 2;
                        mma16816(acc[t][mt][nt], af[mt], bf[nb][pr], bf[nb][pr + 1]);
                    }
            }
        }
        // boundary columns (hidden under other warps' mma)
        if (tid < 128) {
            const __half* arow = (const __half*)(smem + OFF_A + buf * A_BUF) + tid * PA;
            const float* pl = (const float*)(smem + OFF_PL) + c * 32;
            float* sCL = (float*)(smem + OFF_CL);
            float sum = sCL[tid];
            #pragma unroll
            for (int jl = 0; jl < 32; jl++) sum += __half2float(arow[jl]) * pl[jl];
            sCL[tid] = sum;
        } else if (tid < 256) {
            int co = tid - 128;
            const __half* arow = (const __half*)(smem + OFF_A + buf * A_BUF + 2 * A_TAP) + co * PA;
            const float* pr = (const float*)(smem + OFF_PR) + c * 32;
            float* sCR = (float*)(smem + OFF_CR);
            float sum = sCR[co];
            #pragma unroll
            for (int jl = 0; jl < 32; jl++) sum += __half2float(arow[jl]) * pr[jl];
            sCR[co] = sum;
        }
        CP_WAIT(0);
        __syncthreads();
    }

    // ---- dump S0/S1/S2 to SMEM (overlays P, now dead) ----
    #pragma unroll
    for (int t = 0; t < 3; t++)
        #pragma unroll
        for (int mt = 0; mt < 2; mt++)
            #pragma unroll
            for (int nt = 0; nt < 4; nt++) {
                int co = co0 + mt * 16 + (lane >> 2);
                int m  = mbase + nt * 8 + (lane & 3) * 2;
                uint32_t base = sb + OFF_SB + (uint32_t)(t * SB_T + co * (PSB * 2) + m * 2);
                *(uint32_t*)(smem + (base - sb))            = pk(acc[t][mt][nt][0], acc[t][mt][nt][1]);
                *(uint32_t*)(smem + (base - sb) + 8 * (PSB * 2)) = pk(acc[t][mt][nt][2], acc[t][mt][nt][3]);
            }
    __syncthreads();

    // ---- combine: even/odd, stats, write g_mid ----
    {
        const __half* S0 = (const __half*)(smem + OFF_SB);
        const __half* S1 = S0 + SB_T / 2;
        const __half* S2 = S1 + SB_T / 2;
        const float* cl = (const float*)(smem + OFF_CL);
        const float* cr = (const float*)(smem + OFF_CR);
        const int co = tid >> 2, oct0 = tid & 3;
        const float bv = __ldg(&bias[co]);
        const __half* s0 = S0 + co * PSB;
        const __half* s1 = S1 + co * PSB;
        const __half* s2 = S2 + co * PSB;
        float s = 0.f, ss = 0.f;
        #pragma unroll
        for (int i = 0; i < 4; i++) {
            int i0 = (i * 4 + oct0) * 8;      // octet start m
            float s0prev = (i0 == 0) ? cl[co] : __half2float(s0[i0 - 1]);
            float s2cur  = __half2float(s2[i0]);
            uint32_t outw[8];
            #pragma unroll
            for (int u = 0; u < 8; u++) {
                int m = i0 + u;
                float s0c = __half2float(s0[m]);
                float s1c = __half2float(s1[m]);
                float s2n = (m == 127) ? cr[co] : __half2float(s2[m + 1]);
                float e = s0prev + s1c + s2cur + bv;
                float o = s0c + s1c + s2n + bv;
                outw[u] = pk(e, o);
                s  += e + o;
                ss += e * e + o * o;
                s0prev = s0c;
                s2cur  = s2n;
            }
            uint4* dst = (uint4*)(g_mid + (size_t)(b * COUT + co) * LOUT + 2 * m0 + i0 * 2);
            dst[0] = make_uint4(outw[0], outw[1], outw[2], outw[3]);
            dst[1] = make_uint4(outw[4], outw[5], outw[6], outw[7]);
        }
        s  += __shfl_xor_sync(0xffffffffu, s, 1, 4);
        s  += __shfl_xor_sync(0xffffffffu, s, 2, 4);
        ss += __shfl_xor_sync(0xffffffffu, ss, 1, 4);
        ss += __shfl_xor_sync(0xffffffffu, ss, 2, 4);
        if (oct0 == 0) {
            int pidx = (b * NT + tile) * COUT + co;
            g_psum[pidx]   = s;
            g_psumsq[pidx] = ss;
        }
    }
}

// ---------------------------------------------------------------------------
// Kernel 3: fused stats-reduce + normalize + tanh. One block per (b,co) row.
// ---------------------------------------------------------------------------
__global__ __launch_bounds__(256, 8)
void norm_fused(float* __restrict__ out) {
    __shared__ float sstat[2];
    const int row = blockIdx.x;
    const int tid = threadIdx.x;
    if (tid < 32) {
        int b = row >> 7, co = row & 127;
        float s = 0.f, ss = 0.f;
        #pragma unroll
        for (int h = 0; h < 2; h++) {
            int t = tid + h * 32;
            int p = (b * NT + t) * COUT + co;
            s  += g_psum[p];
            ss += g_psumsq[p];
        }
        #pragma unroll
        for (int off = 16; off > 0; off >>= 1) {
            s  += __shfl_xor_sync(0xffffffffu, s, off);
            ss += __shfl_xor_sync(0xffffffffu, ss, off);
        }
        if (tid == 0) {
            double mean = (double)s / (double)LOUT;
            double var  = (double)ss / (double)LOUT - mean * mean;
            sstat[0] = (float)mean;
            sstat[1] = (float)(1.0 / sqrt(var + 1e-5));
        }
    }
    __syncthreads();
    const float mean = sstat[0], rstd = sstat[1];
    const uint4* m8 = (const uint4*)(g_mid + (size_t)row * LOUT);
    float4* o4 = (float4*)(out + (size_t)row * LOUT);
    #pragma unroll
    for (int i = 0; i < 8; i++) {
        int idx = tid + i * 256;
        uint4 v = m8[idx];
        float2 a0 = __half22float2(*(__half2*)&v.x);
        float2 a1 = __half22float2(*(__half2*)&v.y);
        float2 a2 = __half22float2(*(__half2*)&v.z);
        float2 a3 = __half22float2(*(__half2*)&v.w);
        float4 r0, r1;
        r0.x = tanhf((a0.x - mean) * rstd);
        r0.y = tanhf((a0.y - mean) * rstd);
        r0.z = tanhf((a1.x - mean) * rstd);
        r0.w = tanhf((a1.y - mean) * rstd);
        r1.x = tanhf((a2.x - mean) * rstd);
        r1.y = tanhf((a2.y - mean) * rstd);
        r1.z = tanhf((a3.x - mean) * rstd);
        r1.w = tanhf((a3.y - mean) * rstd);
        o4[idx * 2 + 0] = r0;
        o4[idx * 2 + 1] = r1;
    }
}

// ---------------------------------------------------------------------------
extern "C" void kernel_launch(void* const* d_in, const int* in_sizes, int n_in,
                              void* d_out, int out_size) {
    const float* x    = (const float*)d_in[0];
    const float* W    = (const float*)d_in[1];
    const float* bias = (const float*)d_in[2];
    float* out = (float*)d_out;

    cudaFuncSetAttribute(conv_kernel,
                         cudaFuncAttributeMaxDynamicSharedMemorySize, SM_TOTAL);

    prep_weights<<<(COUT * 384 + 255) / 256, 256>>>(W);
    noop<<<1, 32>>>();
    noop<<<1, 32>>>();                  // keeps ncu capture on conv
    conv_kernel<<<dim3(NT, BATCH), 512, SM_TOTAL>>>(x, bias);
    norm_fused<<<BATCH * COUT, 256>>>(out);
}